// round 13
// baseline (speedup 1.0000x reference)
#include <cuda_runtime.h>
#include <cstdint>
#include <cstddef>

#define TT 16            // tokens per tile
#define NC 1024          // flattened stream dim (n*C)
#define NTHR 384
#define FULLMASK 0xFFFFFFFFu

typedef unsigned long long ull;

// ---- packed f32x2 helpers (Blackwell FFMA2 path) ----
__device__ __forceinline__ void fma2(ull &acc, ull a, ull b) {
    asm("fma.rn.f32x2 %0, %1, %2, %0;" : "+l"(acc) : "l"(a), "l"(b));
}
__device__ __forceinline__ ull pack2(float x, float y) {
    ull r;
    asm("mov.b64 %0, {%1, %2};" : "=l"(r)
        : "r"(__float_as_uint(x)), "r"(__float_as_uint(y)));
    return r;
}
__device__ __forceinline__ float hadd2(ull v) {
    unsigned lo, hi;
    asm("mov.b64 {%0, %1}, %2;" : "=r"(lo), "=r"(hi) : "l"(v));
    return __uint_as_float(lo) + __uint_as_float(hi);
}

__device__ __forceinline__ void cp_async16(uint32_t saddr, const void* gaddr) {
    asm volatile("cp.async.cg.shared.global [%0], [%1], 16;"
                 :: "r"(saddr), "l"(gaddr));
}

// smem (floats): xbuf[3][TT*NC] | dotsp[2][TT][24] | sqsm[2][TT] | coef[2][TT*16] | bsm[32]
#define SMEM_FLOATS (3*TT*NC + 2*TT*24 + 2*TT + 2*TT*16 + 32)

__global__ __launch_bounds__(NTHR, 1)
void fused_streams_kernel(const float* __restrict__ x,
                          const float* __restrict__ scale,
                          const float* __restrict__ w_pre,
                          const float* __restrict__ w_post,
                          const float* __restrict__ w_res,
                          const float* __restrict__ p_apre,
                          const float* __restrict__ p_apost,
                          const float* __restrict__ p_ares,
                          const float* __restrict__ b_pre,
                          const float* __restrict__ b_post,
                          const float* __restrict__ b_res,
                          float* __restrict__ out,
                          int nTiles)
{
    extern __shared__ float smem[];
    float* xb3   = smem;                      // 3 x-buffers
    float* dotsp = smem + 3*TT*NC;            // [2][TT][24]
    float* sqsm  = dotsp + 2*TT*24;           // [2][TT]
    float* coef  = sqsm + 2*TT;               // [2][TT*16]
    float* bsm   = coef + 2*TT*16;            // [24] biases

    const int tid  = threadIdx.x;
    const int lane = tid & 31;
    const int warp = tid >> 5;            // 0..11
    const int g    = warp >> 1;           // row group 0..5 (4 rows each)
    const int kh   = warp & 1;            // K-half 0/1
    const bool b16 = (lane & 16) != 0;
    const bool b8  = (lane & 8)  != 0;
    const bool b4  = (lane & 4)  != 0;

    const float a_pre  = *p_apre;
    const float a_post = *p_apost;
    const float a_res  = *p_ares;

    // biases into smem (once)
    if (tid < 4)        bsm[tid] = b_pre[tid];
    else if (tid < 8)   bsm[tid] = b_post[tid - 4];
    else if (tid < 24)  bsm[tid] = b_res[tid - 8];

    // ---- weight slice into registers (scale folded) ----
    // warp (g,kh): rows 4g..4g+3, K-half kh. Lane l owns float4 chunks
    // idx = kh*128 + l + 32m, m=0..3 -> 8 ull per row, 4 rows = 32 ull
    ull wr[4][8];
#pragma unroll
    for (int q = 0; q < 4; q++) {
        int r = g*4 + q;
        const float* wrow = (r < 4)  ? (w_pre  + r*NC)
                          : (r < 8)  ? (w_post + (r-4)*NC)
                                     : (w_res  + (r-8)*NC);
        const float4* wrow4 = reinterpret_cast<const float4*>(wrow);
        const float4* sc4   = reinterpret_cast<const float4*>(scale);
#pragma unroll
        for (int m = 0; m < 4; m++) {
            int idx = kh*128 + lane + 32*m;
            float4 wv = wrow4[idx];
            float4 sv = sc4[idx];
            wr[q][2*m]   = pack2(wv.x * sv.x, wv.y * sv.y);
            wr[q][2*m+1] = pack2(wv.z * sv.z, wv.w * sv.w);
        }
    }

    uint32_t sbase = (uint32_t)__cvta_generic_to_shared(xb3);

    int tile = blockIdx.x;
    const int stride = gridDim.x;

    // ---- prime: prefetch tile -> buf0, tile+stride -> buf1 ----
    if (tile < nTiles) {
        const char* src = (const char*)(x + (size_t)tile * (TT*NC));
#pragma unroll
        for (int j = 0; j < 11; j++) {
            int off = j*6144 + tid*16;
            if (off < TT*NC*4) cp_async16(sbase + off, src + off);
        }
    }
    asm volatile("cp.async.commit_group;");
    if (tile + stride < nTiles) {
        const char* src = (const char*)(x + (size_t)(tile + stride) * (TT*NC));
#pragma unroll
        for (int j = 0; j < 11; j++) {
            int off = j*6144 + tid*16;
            if (off < TT*NC*4) cp_async16(sbase + TT*NC*4 + off, src + off);
        }
    }
    asm volatile("cp.async.commit_group;");

    int bi = 0;                 // buffer of current tile
    int cpar = 0;               // coef parity of current tile
    bool have_prev = false;
    int prevTile = 0, prevBuf = 0;

    for (; tile < nTiles; tile += stride) {
        asm volatile("cp.async.wait_group 1;");   // x(tile) resident
        __syncthreads();

        const float* xb = xb3 + bi*(TT*NC);

        // ---- Phase B: dots (+ folded x^2), warp = 4 rows x K/2 ----
#pragma unroll
        for (int t = 0; t < TT; t += 2) {
            const bool doSq = (g == 0 && t < 8) || (g == 1 && t >= 8);

            const float4* xA = reinterpret_cast<const float4*>(xb + t*NC)     + kh*128;
            const float4* xB = reinterpret_cast<const float4*>(xb + (t+1)*NC) + kh*128;
            ull av[8], bv[8];
#pragma unroll
            for (int m = 0; m < 4; m++) {
                float4 va = xA[lane + 32*m];
                float4 vb = xB[lane + 32*m];
                av[2*m]   = pack2(va.x, va.y);
                av[2*m+1] = pack2(va.z, va.w);
                bv[2*m]   = pack2(vb.x, vb.y);
                bv[2*m+1] = pack2(vb.z, vb.w);
            }
            ull acc[8];
#pragma unroll
            for (int q = 0; q < 8; q++) acc[q] = 0ull;
#pragma unroll
            for (int m = 0; m < 8; m++) {
#pragma unroll
                for (int q = 0; q < 4; q++) {
                    fma2(acc[q],   wr[q][m], av[m]);
                    fma2(acc[4+q], wr[q][m], bv[m]);
                }
            }
            ull sqa = 0ull, sqb = 0ull;
            if (doSq) {
#pragma unroll
                for (int m = 0; m < 8; m++) {
                    fma2(sqa, av[m], av[m]);
                    fma2(sqb, bv[m], bv[m]);
                }
            }

            float v[8];
#pragma unroll
            for (int q = 0; q < 8; q++) v[q] = hadd2(acc[q]);

            // keep/send butterfly: 9 SHFL total
            // level 16: split tokens (b16=0 -> token t, b16=1 -> token t+1)
            float u0, u1, u2, u3;
            {
                float k0 = b16 ? v[4] : v[0], s0 = b16 ? v[0] : v[4];
                float k1 = b16 ? v[5] : v[1], s1 = b16 ? v[1] : v[5];
                float k2 = b16 ? v[6] : v[2], s2 = b16 ? v[2] : v[6];
                float k3 = b16 ? v[7] : v[3], s3 = b16 ? v[3] : v[7];
                u0 = k0 + __shfl_xor_sync(FULLMASK, s0, 16);
                u1 = k1 + __shfl_xor_sync(FULLMASK, s1, 16);
                u2 = k2 + __shfl_xor_sync(FULLMASK, s2, 16);
                u3 = k3 + __shfl_xor_sync(FULLMASK, s3, 16);
            }
            // level 8: split row pairs (b8=0 -> rows{0,1}, b8=1 -> rows{2,3})
            float w0, w1;
            {
                float k0 = b8 ? u2 : u0, s0 = b8 ? u0 : u2;
                float k1 = b8 ? u3 : u1, s1 = b8 ? u1 : u3;
                w0 = k0 + __shfl_xor_sync(FULLMASK, s0, 8);
                w1 = k1 + __shfl_xor_sync(FULLMASK, s1, 8);
            }
            // level 4: split row parity
            float y;
            {
                float k = b4 ? w1 : w0, s = b4 ? w0 : w1;
                y = k + __shfl_xor_sync(FULLMASK, s, 4);
            }
            y += __shfl_xor_sync(FULLMASK, y, 2);
            y += __shfl_xor_sync(FULLMASK, y, 1);
            if ((lane & 3) == 0) {
                int tok = t + (b16 ? 1 : 0);
                int row = (b8 ? 2 : 0) + (b4 ? 1 : 0);
                dotsp[(kh*TT + tok)*24 + g*4 + row] = y;
            }
            if (doSq) {
                float s0 = hadd2(sqa), s1 = hadd2(sqb);
                float kk = b16 ? s1 : s0, ss = b16 ? s0 : s1;
                float s = kk + __shfl_xor_sync(FULLMASK, ss, 16);
                s += __shfl_xor_sync(FULLMASK, s, 8);
                s += __shfl_xor_sync(FULLMASK, s, 4);
                s += __shfl_xor_sync(FULLMASK, s, 2);
                s += __shfl_xor_sync(FULLMASK, s, 1);
                if ((lane & 15) == 0)
                    sqsm[kh*TT + t + (b16 ? 1 : 0)] = s;
            }
        }
        __syncthreads();

        // ---- Phase C (threads 0..15, tile i)  ||  Phase D (threads 32.., tile i-1) ----
        if (tid < TT) {
            int t = tid;
            float rs = rsqrtf((sqsm[t] + sqsm[TT + t]) * (1.0f/1024.0f) + 1e-5f);
            float ar = a_res * rs;
            const float4* p0 = reinterpret_cast<const float4*>(dotsp + t*24);
            const float4* p1 = reinterpret_cast<const float4*>(dotsp + (TT + t)*24);

            float4 s2 = p0[2], s3 = p0[3], s4 = p0[4], s5 = p0[5], qv;
            qv = p1[2]; s2.x+=qv.x; s2.y+=qv.y; s2.z+=qv.z; s2.w+=qv.w;
            qv = p1[3]; s3.x+=qv.x; s3.y+=qv.y; s3.z+=qv.z; s3.w+=qv.w;
            qv = p1[4]; s4.x+=qv.x; s4.y+=qv.y; s4.z+=qv.z; s4.w+=qv.w;
            qv = p1[5]; s5.x+=qv.x; s5.y+=qv.y; s5.z+=qv.z; s5.w+=qv.w;

            float4 z0 = make_float4(fmaf(ar, s2.x, bsm[8]),  fmaf(ar, s2.y, bsm[9]),
                                    fmaf(ar, s2.z, bsm[10]), fmaf(ar, s2.w, bsm[11]));
            float4 z1 = make_float4(fmaf(ar, s3.x, bsm[12]), fmaf(ar, s3.y, bsm[13]),
                                    fmaf(ar, s3.z, bsm[14]), fmaf(ar, s3.w, bsm[15]));
            float4 z2 = make_float4(fmaf(ar, s4.x, bsm[16]), fmaf(ar, s4.y, bsm[17]),
                                    fmaf(ar, s4.z, bsm[18]), fmaf(ar, s4.w, bsm[19]));
            float4 z3 = make_float4(fmaf(ar, s5.x, bsm[20]), fmaf(ar, s5.y, bsm[21]),
                                    fmaf(ar, s5.z, bsm[22]), fmaf(ar, s5.w, bsm[23]));

            float mx = fmaxf(fmaxf(fmaxf(z0.x, z0.y), fmaxf(z0.z, z0.w)),
                      fmaxf(fmaxf(fmaxf(z1.x, z1.y), fmaxf(z1.z, z1.w)),
                      fmaxf(fmaxf(fmaxf(z2.x, z2.y), fmaxf(z2.z, z2.w)),
                            fmaxf(fmaxf(z3.x, z3.y), fmaxf(z3.z, z3.w)))));
            float4 q0 = make_float4(__expf(z0.x-mx), __expf(z0.y-mx), __expf(z0.z-mx), __expf(z0.w-mx));
            float4 q1 = make_float4(__expf(z1.x-mx), __expf(z1.y-mx), __expf(z1.z-mx), __expf(z1.w-mx));
            float4 q2 = make_float4(__expf(z2.x-mx), __expf(z2.y-mx), __expf(z2.z-mx), __expf(z2.w-mx));
            float4 q3 = make_float4(__expf(z3.x-mx), __expf(z3.y-mx), __expf(z3.z-mx), __expf(z3.w-mx));

#pragma unroll
            for (int it = 0; it < 20; it++) {
                float4 ic;
                ic.x = __fdividef(1.f, (q0.x + q1.x) + (q2.x + q3.x) + 1e-8f);
                ic.y = __fdividef(1.f, (q0.y + q1.y) + (q2.y + q3.y) + 1e-8f);
                ic.z = __fdividef(1.f, (q0.z + q1.z) + (q2.z + q3.z) + 1e-8f);
                ic.w = __fdividef(1.f, (q0.w + q1.w) + (q2.w + q3.w) + 1e-8f);
                q0.x *= ic.x; q0.y *= ic.y; q0.z *= ic.z; q0.w *= ic.w;
                q1.x *= ic.x; q1.y *= ic.y; q1.z *= ic.z; q1.w *= ic.w;
                q2.x *= ic.x; q2.y *= ic.y; q2.z *= ic.z; q2.w *= ic.w;
                q3.x *= ic.x; q3.y *= ic.y; q3.z *= ic.z; q3.w *= ic.w;
                float i0 = __fdividef(1.f, (q0.x + q0.y) + (q0.z + q0.w) + 1e-8f);
                float i1 = __fdividef(1.f, (q1.x + q1.y) + (q1.z + q1.w) + 1e-8f);
                float i2 = __fdividef(1.f, (q2.x + q2.y) + (q2.z + q2.w) + 1e-8f);
                float i3 = __fdividef(1.f, (q3.x + q3.y) + (q3.z + q3.w) + 1e-8f);
                q0.x *= i0; q0.y *= i0; q0.z *= i0; q0.w *= i0;
                q1.x *= i1; q1.y *= i1; q1.z *= i1; q1.w *= i1;
                q2.x *= i2; q2.y *= i2; q2.z *= i2; q2.w *= i2;
                q3.x *= i3; q3.y *= i3; q3.z *= i3; q3.w *= i3;
            }

            // gates
            const float* d0 = dotsp + t*24;
            const float* d1 = dotsp + (TT + t)*24;
            float hpre[4], hpost[4];
#pragma unroll
            for (int r = 0; r < 4; r++) {
                float dd = d0[r] + d1[r];
                hpre[r] = __fdividef(1.0f, 1.0f + __expf(-fmaf(a_pre, dd*rs, bsm[r])));
            }
#pragma unroll
            for (int r = 0; r < 4; r++) {
                float dd = d0[4+r] + d1[4+r];
                hpost[r] = __fdividef(2.0f, 1.0f + __expf(-fmaf(a_post, dd*rs, bsm[4+r])));
            }
            float4* cf4 = reinterpret_cast<float4*>(coef + cpar*(TT*16) + t*16);
            cf4[0] = make_float4(fmaf(hpost[0], hpre[0], q0.x), fmaf(hpost[0], hpre[1], q0.y),
                                 fmaf(hpost[0], hpre[2], q0.z), fmaf(hpost[0], hpre[3], q0.w));
            cf4[1] = make_float4(fmaf(hpost[1], hpre[0], q1.x), fmaf(hpost[1], hpre[1], q1.y),
                                 fmaf(hpost[1], hpre[2], q1.z), fmaf(hpost[1], hpre[3], q1.w));
            cf4[2] = make_float4(fmaf(hpost[2], hpre[0], q2.x), fmaf(hpost[2], hpre[1], q2.y),
                                 fmaf(hpost[2], hpre[2], q2.z), fmaf(hpost[2], hpre[3], q2.w));
            cf4[3] = make_float4(fmaf(hpost[3], hpre[0], q3.x), fmaf(hpost[3], hpre[1], q3.y),
                                 fmaf(hpost[3], hpre[2], q3.z), fmaf(hpost[3], hpre[3], q3.w));
        } else if (tid >= 32 && have_prev) {
            // Phase D for previous tile on warps 1..11
            const float* xp = xb3 + prevBuf*(TT*NC);
            const float4* cf4 = reinterpret_cast<const float4*>(coef + (cpar^1)*(TT*16));
            int idx = tid - 32;
            for (int i = idx; i < 1024; i += 352) {
                int t  = i >> 6;
                int c4 = i & 63;
                float4 m0 = cf4[t*4 + 0];
                float4 m1 = cf4[t*4 + 1];
                float4 m2 = cf4[t*4 + 2];
                float4 m3 = cf4[t*4 + 3];
                const float4* x4 = reinterpret_cast<const float4*>(xp) + t*256;
                float4 xj0 = x4[0*64 + c4];
                float4 xj1 = x4[1*64 + c4];
                float4 xj2 = x4[2*64 + c4];
                float4 xj3 = x4[3*64 + c4];
                float4* o4 = reinterpret_cast<float4*>(out)
                           + ((size_t)prevTile*TT + t) * 256;
                float4 o;
                o.x = m0.x*xj0.x + m0.y*xj1.x + m0.z*xj2.x + m0.w*xj3.x;
                o.y = m0.x*xj0.y + m0.y*xj1.y + m0.z*xj2.y + m0.w*xj3.y;
                o.z = m0.x*xj0.z + m0.y*xj1.z + m0.z*xj2.z + m0.w*xj3.z;
                o.w = m0.x*xj0.w + m0.y*xj1.w + m0.z*xj2.w + m0.w*xj3.w;
                __stcs(&o4[0*64 + c4], o);
                o.x = m1.x*xj0.x + m1.y*xj1.x + m1.z*xj2.x + m1.w*xj3.x;
                o.y = m1.x*xj0.y + m1.y*xj1.y + m1.z*xj2.y + m1.w*xj3.y;
                o.z = m1.x*xj0.z + m1.y*xj1.z + m1.z*xj2.z + m1.w*xj3.z;
                o.w = m1.x*xj0.w + m1.y*xj1.w + m1.z*xj2.w + m1.w*xj3.w;
                __stcs(&o4[1*64 + c4], o);
                o.x = m2.x*xj0.x + m2.y*xj1.x + m2.z*xj2.x + m2.w*xj3.x;
                o.y = m2.x*xj0.y + m2.y*xj1.y + m2.z*xj2.y + m2.w*xj3.y;
                o.z = m2.x*xj0.z + m2.y*xj1.z + m2.z*xj2.z + m2.w*xj3.z;
                o.w = m2.x*xj0.w + m2.y*xj1.w + m2.z*xj2.w + m2.w*xj3.w;
                __stcs(&o4[2*64 + c4], o);
                o.x = m3.x*xj0.x + m3.y*xj1.x + m3.z*xj2.x + m3.w*xj3.x;
                o.y = m3.x*xj0.y + m3.y*xj1.y + m3.z*xj2.y + m3.w*xj3.y;
                o.z = m3.x*xj0.z + m3.y*xj1.z + m3.z*xj2.z + m3.w*xj3.z;
                o.w = m3.x*xj0.w + m3.y*xj1.w + m3.z*xj2.w + m3.w*xj3.w;
                __stcs(&o4[3*64 + c4], o);
            }
        }
        __syncthreads();   // D done reading prev buffer; coef(i) ready

        // prefetch tile+2*stride into the buffer D just released
        {
            int nxt2 = tile + 2*stride;
            int pb = (bi >= 1) ? (bi - 1) : 2;   // (bi+2)%3
            if (nxt2 < nTiles) {
                const char* src = (const char*)(x + (size_t)nxt2 * (TT*NC));
                uint32_t sbn = sbase + (uint32_t)pb * (TT*NC*4);
#pragma unroll
                for (int j = 0; j < 11; j++) {
                    int off = j*6144 + tid*16;
                    if (off < TT*NC*4) cp_async16(sbn + off, src + off);
                }
            }
            asm volatile("cp.async.commit_group;");
        }

        have_prev = true;
        prevTile = tile;
        prevBuf = bi;
        bi = (bi == 2) ? 0 : bi + 1;
        cpar ^= 1;
    }

    // ---- epilogue: Phase D for the last tile, all threads ----
    if (have_prev) {
        const float* xp = xb3 + prevBuf*(TT*NC);
        const float4* cf4 = reinterpret_cast<const float4*>(coef + (cpar^1)*(TT*16));
        for (int i = tid; i < 1024; i += NTHR) {
            int t  = i >> 6;
            int c4 = i & 63;
            float4 m0 = cf4[t*4 + 0];
            float4 m1 = cf4[t*4 + 1];
            float4 m2 = cf4[t*4 + 2];
            float4 m3 = cf4[t*4 + 3];
            const float4* x4 = reinterpret_cast<const float4*>(xp) + t*256;
            float4 xj0 = x4[0*64 + c4];
            float4 xj1 = x4[1*64 + c4];
            float4 xj2 = x4[2*64 + c4];
            float4 xj3 = x4[3*64 + c4];
            float4* o4 = reinterpret_cast<float4*>(out)
                       + ((size_t)prevTile*TT + t) * 256;
            float4 o;
            o.x = m0.x*xj0.x + m0.y*xj1.x + m0.z*xj2.x + m0.w*xj3.x;
            o.y = m0.x*xj0.y + m0.y*xj1.y + m0.z*xj2.y + m0.w*xj3.y;
            o.z = m0.x*xj0.z + m0.y*xj1.z + m0.z*xj2.z + m0.w*xj3.z;
            o.w = m0.x*xj0.w + m0.y*xj1.w + m0.z*xj2.w + m0.w*xj3.w;
            __stcs(&o4[0*64 + c4], o);
            o.x = m1.x*xj0.x + m1.y*xj1.x + m1.z*xj2.x + m1.w*xj3.x;
            o.y = m1.x*xj0.y + m1.y*xj1.y + m1.z*xj2.y + m1.w*xj3.y;
            o.z = m1.x*xj0.z + m1.y*xj1.z + m1.z*xj2.z + m1.w*xj3.z;
            o.w = m1.x*xj0.w + m1.y*xj1.w + m1.z*xj2.w + m1.w*xj3.w;
            __stcs(&o4[1*64 + c4], o);
            o.x = m2.x*xj0.x + m2.y*xj1.x + m2.z*xj2.x + m2.w*xj3.x;
            o.y = m2.x*xj0.y + m2.y*xj1.y + m2.z*xj2.y + m2.w*xj3.y;
            o.z = m2.x*xj0.z + m2.y*xj1.z + m2.z*xj2.z + m2.w*xj3.z;
            o.w = m2.x*xj0.w + m2.y*xj1.w + m2.z*xj2.w + m2.w*xj3.w;
            __stcs(&o4[2*64 + c4], o);
            o.x = m3.x*xj0.x + m3.y*xj1.x + m3.z*xj2.x + m3.w*xj3.x;
            o.y = m3.x*xj0.y + m3.y*xj1.y + m3.z*xj2.y + m3.w*xj3.y;
            o.z = m3.x*xj0.z + m3.y*xj1.z + m3.z*xj2.z + m3.w*xj3.z;
            o.w = m3.x*xj0.w + m3.y*xj1.w + m3.z*xj2.w + m3.w*xj3.w;
            __stcs(&o4[3*64 + c4], o);
        }
    }
}

extern "C" void kernel_launch(void* const* d_in, const int* in_sizes, int n_in,
                              void* d_out, int out_size) {
    const float* x      = (const float*)d_in[0];
    const float* scale  = (const float*)d_in[1];
    const float* w_pre  = (const float*)d_in[2];
    const float* w_post = (const float*)d_in[3];
    const float* w_res  = (const float*)d_in[4];
    const float* apre   = (const float*)d_in[5];
    const float* apost  = (const float*)d_in[6];
    const float* ares   = (const float*)d_in[7];
    const float* b_pre  = (const float*)d_in[8];
    const float* b_post = (const float*)d_in[9];
    const float* b_res  = (const float*)d_in[10];
    float* out = (float*)d_out;

    int BT = in_sizes[0] / NC;        // 32768 tokens
    int nTiles = BT / TT;             // 2048

    size_t smemBytes = (size_t)SMEM_FLOATS * sizeof(float);   // ~197 KB

    int dev = 0;
    cudaGetDevice(&dev);
    int sms = 148;
    cudaDeviceGetAttribute(&sms, cudaDevAttrMultiProcessorCount, dev);
    cudaFuncSetAttribute(fused_streams_kernel,
                         cudaFuncAttributeMaxDynamicSharedMemorySize,
                         (int)smemBytes);

    int grid = sms < nTiles ? sms : nTiles;

    fused_streams_kernel<<<grid, NTHR, smemBytes>>>(
        x, scale, w_pre, w_post, w_res,
        apre, apost, ares, b_pre, b_post, b_res,
        out, nTiles);
}